// round 4
// baseline (speedup 1.0000x reference)
#include <cuda_runtime.h>
#include <cuda_bf16.h>
#include <cstdint>

// Problem constants
#define N_TOK 262144
#define DIM   64
#define KCB   512
#define GAMMA 0.99f

#define TPB     256
#define TOK_CTA 256
#define MARGIN  1e-3f    // >= 5x worst-case coarse-score error (~2e-4)

// smem layout: codebook hi | mid (SW128-swizzled) | bias
#define SM_B_HI   0
#define SM_B_MID  65536
#define SM_BIAS   131072
#define SMEM_BYTES (SM_BIAS + 2048)

#define SW(o) ((o) ^ (((o) >> 3) & 0x70))

// device globals (allocation-free scratch)
__device__ __align__(16) __nv_bfloat16 g_vq_hi[KCB * DIM];
__device__ __align__(16) __nv_bfloat16 g_vq_mid[KCB * DIM];
__device__ float g_bias[KCB];      // 0.5*||v_k||^2
__device__ float g_cs[KCB * DIM];  // zero at load; finalize re-zeros
__device__ float g_cn[KCB];

// ---------------- helpers ----------------
__device__ __forceinline__ uint32_t smem_u32(const void* p) {
    uint32_t a;
    asm("{ .reg .u64 t; cvta.to.shared.u64 t, %1; cvt.u32.u64 %0, t; }" : "=r"(a) : "l"(p));
    return a;
}
__device__ __forceinline__ uint32_t pack_bf(__nv_bfloat16 a, __nv_bfloat16 b) {
    __nv_bfloat162 t(a, b);
    return *reinterpret_cast<uint32_t*>(&t);
}
__device__ __forceinline__ void split2(float2 f, uint32_t& h, uint32_t& m) {
    __nv_bfloat16 ha = __float2bfloat16(f.x), hb = __float2bfloat16(f.y);
    __nv_bfloat16 ma = __float2bfloat16(f.x - __bfloat162float(ha));
    __nv_bfloat16 mb = __float2bfloat16(f.y - __bfloat162float(hb));
    h = pack_bf(ha, hb);
    m = pack_bf(ma, mb);
}

#define LDMX4(R, A) \
    asm volatile("ldmatrix.sync.aligned.m8n8.x4.shared.b16 {%0,%1,%2,%3}, [%4];" \
                 : "=r"((R)[0]), "=r"((R)[1]), "=r"((R)[2]), "=r"((R)[3]) : "r"(A))

#define MMA(C, A, B0, B1) \
    asm volatile("mma.sync.aligned.m16n8k16.row.col.f32.bf16.bf16.f32 " \
                 "{%0,%1,%2,%3}, {%4,%5,%6,%7}, {%8,%9}, {%0,%1,%2,%3};" \
                 : "+f"((C)[0]), "+f"((C)[1]), "+f"((C)[2]), "+f"((C)[3]) \
                 : "r"((A)[0]), "r"((A)[1]), "r"((A)[2]), "r"((A)[3]), "r"(B0), "r"(B1))

// ---------------- init: bf16 hi/mid codebook + bias ----------------
__global__ void init_kernel(const float* __restrict__ vq) {
    __shared__ float sh[2];
    int k = blockIdx.x, d = threadIdx.x;
    float v = vq[k * DIM + d];
    __nv_bfloat16 h = __float2bfloat16(v);
    g_vq_hi[k * DIM + d] = h;
    g_vq_mid[k * DIM + d] = __float2bfloat16(v - __bfloat162float(h));
    float s = v * v;
    #pragma unroll
    for (int o = 16; o > 0; o >>= 1) s += __shfl_down_sync(0xffffffffu, s, o);
    if ((d & 31) == 0) sh[d >> 5] = s;
    __syncthreads();
    if (d == 0) g_bias[k] = 0.5f * (sh[0] + sh[1]);
}

// ---------------- assign: HMMA scores + in-register margin-exact argmax ------
__device__ __forceinline__ void upd(float v, int kk, float& best, float& second, int& bk) {
    if (v > best) { second = best; best = v; bk = kk; }
    else          { second = fmaxf(second, v); }
}

__global__ void __launch_bounds__(TPB, 1) assign_kernel(
    const float* __restrict__ x,
    const float* __restrict__ vq,
    float* __restrict__ q_out)
{
    extern __shared__ __align__(1024) char smem[];
    float* sbias = reinterpret_cast<float*>(smem + SM_BIAS);
    const uint32_t sb = smem_u32(smem);
    const int tid = threadIdx.x;
    const int lane = tid & 31, wid = tid >> 5;
    const int g = lane >> 2, c = lane & 3;

    // ---- stage codebook (hi|mid) into swizzled smem + bias ----
    for (int i = tid; i < 8192; i += TPB) {
        uint32_t off = SW((uint32_t)((i & 4095) * 16));
        if (i < 4096)
            *reinterpret_cast<uint4*>(smem + SM_B_HI + off) = reinterpret_cast<const uint4*>(g_vq_hi)[i];
        else
            *reinterpret_cast<uint4*>(smem + SM_B_MID + off) = reinterpret_cast<const uint4*>(g_vq_mid)[i - 4096];
    }
    for (int i = tid; i < KCB; i += TPB) sbias[i] = g_bias[i];

    // ---- A fragments: warp's 32 token rows x 64 dims, hi+mid, in registers ----
    uint32_t a_hi[2][4][4], a_mid[2][4][4];
    const int rowbase = blockIdx.x * TOK_CTA + wid * 32;
    #pragma unroll
    for (int m = 0; m < 2; m++) {
        #pragma unroll
        for (int kt = 0; kt < 4; kt++) {
            const float* p = x + (size_t)(rowbase + m * 16 + g) * DIM + kt * 16 + 2 * c;
            float2 f0 = *reinterpret_cast<const float2*>(p);            // (R0, K0)
            float2 f1 = *reinterpret_cast<const float2*>(p + 8);        // (R0, K0+8)
            float2 f2 = *reinterpret_cast<const float2*>(p + 8 * DIM);  // (R1, K0)
            float2 f3 = *reinterpret_cast<const float2*>(p + 8 * DIM + 8);
            split2(f0, a_hi[m][kt][0], a_mid[m][kt][0]);
            split2(f2, a_hi[m][kt][1], a_mid[m][kt][1]);
            split2(f1, a_hi[m][kt][2], a_mid[m][kt][2]);
            split2(f3, a_hi[m][kt][3], a_mid[m][kt][3]);
        }
    }
    __syncthreads();

    // running (best, second, k) per C-frag row slot: row = g + 8*s
    float best[4]   = {-3.4e38f, -3.4e38f, -3.4e38f, -3.4e38f};
    float second[4] = {-3.4e38f, -3.4e38f, -3.4e38f, -3.4e38f};
    int   bk[4]     = {0, 0, 0, 0};

    #pragma unroll 1
    for (int n8 = 0; n8 < 64; n8 += 2) {
        const int n0 = n8 * 8;
        float2 biasA = *reinterpret_cast<const float2*>(&sbias[n0 + 2 * c]);
        float2 biasB = *reinterpret_cast<const float2*>(&sbias[n0 + 8 + 2 * c]);
        float CA[2][4], CB[2][4];
        #pragma unroll
        for (int m = 0; m < 2; m++) {
            CA[m][0] = -biasA.x; CA[m][1] = -biasA.y; CA[m][2] = -biasA.x; CA[m][3] = -biasA.y;
            CB[m][0] = -biasB.x; CB[m][1] = -biasB.y; CB[m][2] = -biasB.x; CB[m][3] = -biasB.y;
        }
        #pragma unroll
        for (int kh = 0; kh < 2; kh++) {
            // ldmatrix.x4: matrices (kt=2kh, 2kh+1); lanes 0-7 rows, 8-15 +16B, 16-23 +32B, 24-31 +48B
            uint32_t kb = kh * 64 + ((lane >> 3) * 16);
            uint32_t offA = SW((uint32_t)((n0 + (lane & 7)) * 128) + kb);
            uint32_t offB = SW((uint32_t)((n0 + 8 + (lane & 7)) * 128) + kb);
            uint32_t bhA[4], bmA[4], bhB[4], bmB[4];
            LDMX4(bhA, sb + SM_B_HI + offA);
            LDMX4(bmA, sb + SM_B_MID + offA);
            LDMX4(bhB, sb + SM_B_HI + offB);
            LDMX4(bmB, sb + SM_B_MID + offB);
            #pragma unroll
            for (int kk = 0; kk < 2; kk++) {
                const int kt = kh * 2 + kk;
                #pragma unroll
                for (int m = 0; m < 2; m++) {
                    MMA(CA[m], a_hi[m][kt],  bhA[2 * kk], bhA[2 * kk + 1]);
                    MMA(CA[m], a_hi[m][kt],  bmA[2 * kk], bmA[2 * kk + 1]);
                    MMA(CA[m], a_mid[m][kt], bhA[2 * kk], bhA[2 * kk + 1]);
                    MMA(CB[m], a_hi[m][kt],  bhB[2 * kk], bhB[2 * kk + 1]);
                    MMA(CB[m], a_hi[m][kt],  bmB[2 * kk], bmB[2 * kk + 1]);
                    MMA(CB[m], a_mid[m][kt], bhB[2 * kk], bhB[2 * kk + 1]);
                }
            }
        }
        // running argmax update; slot s holds row g+8s; cols n0+2c{+1} / n0+8+2c{+1}
        const int kA = n0 + 2 * c, kB = n0 + 8 + 2 * c;
        upd(CA[0][0], kA, best[0], second[0], bk[0]); upd(CA[0][1], kA + 1, best[0], second[0], bk[0]);
        upd(CA[0][2], kA, best[1], second[1], bk[1]); upd(CA[0][3], kA + 1, best[1], second[1], bk[1]);
        upd(CA[1][0], kA, best[2], second[2], bk[2]); upd(CA[1][1], kA + 1, best[2], second[2], bk[2]);
        upd(CA[1][2], kA, best[3], second[3], bk[3]); upd(CA[1][3], kA + 1, best[3], second[3], bk[3]);
        upd(CB[0][0], kB, best[0], second[0], bk[0]); upd(CB[0][1], kB + 1, best[0], second[0], bk[0]);
        upd(CB[0][2], kB, best[1], second[1], bk[1]); upd(CB[0][3], kB + 1, best[1], second[1], bk[1]);
        upd(CB[1][0], kB, best[2], second[2], bk[2]); upd(CB[1][1], kB + 1, best[2], second[2], bk[2]);
        upd(CB[1][2], kB, best[3], second[3], bk[3]); upd(CB[1][3], kB + 1, best[3], second[3], bk[3]);
    }

    // ---- quad merge (cols spread over lanes c=0..3 of each group g) ----
    #pragma unroll
    for (int mask = 1; mask <= 2; mask <<= 1) {
        #pragma unroll
        for (int s = 0; s < 4; s++) {
            float ob = __shfl_xor_sync(0xffffffffu, best[s], mask);
            float os = __shfl_xor_sync(0xffffffffu, second[s], mask);
            int   ok = __shfl_xor_sync(0xffffffffu, bk[s], mask);
            if (ob > best[s]) {
                second[s] = fmaxf(best[s], fmaxf(os, second[s]));
                best[s] = ob; bk[s] = ok;
            } else {
                second[s] = fmaxf(second[s], fmaxf(os, ob));
            }
        }
    }
    // redistribute: thread (row L = lane) takes slot L>>3 from lane 4*(L&7)
    float myBest = 0.0f, mySecond = 0.0f;
    int myK = 0;
    #pragma unroll
    for (int s = 0; s < 4; s++) {
        float b  = __shfl_sync(0xffffffffu, best[s],   (lane & 7) * 4);
        float sc = __shfl_sync(0xffffffffu, second[s], (lane & 7) * 4);
        int   kk = __shfl_sync(0xffffffffu, bk[s],     (lane & 7) * 4);
        if ((lane >> 3) == s) { myBest = b; mySecond = sc; myK = kk; }
    }

    // ---- epilogue: per-token (thread t <-> token t) ----
    const int tok = blockIdx.x * TOK_CTA + tid;

    float xr[DIM];
    {
        const float4* xp = reinterpret_cast<const float4*>(x + (size_t)tok * DIM);
        #pragma unroll
        for (int i = 0; i < DIM / 4; i++) {
            float4 t = xp[i];
            xr[4 * i] = t.x; xr[4 * i + 1] = t.y; xr[4 * i + 2] = t.z; xr[4 * i + 3] = t.w;
        }
    }

    int best_k = myK;
    if (mySecond >= myBest - MARGIN) {
        // rare (~0.05%): exact fp32 rescan of all 512 codewords
        float be = -3.4e38f;
        int bkk = 0;
        #pragma unroll 1
        for (int k = 0; k < KCB; k++) {
            const float* vr = vq + (size_t)k * DIM;
            float acc0 = 0.0f, acc1 = 0.0f;
            #pragma unroll
            for (int d = 0; d < DIM; d += 2) {
                acc0 = fmaf(xr[d],     __ldg(vr + d),     acc0);
                acc1 = fmaf(xr[d + 1], __ldg(vr + d + 1), acc1);
            }
            float s = (acc0 + acc1) - sbias[k];
            if (s > be) { be = s; bkk = k; }   // strict >: lowest k wins ties
        }
        best_k = bkk;
    }

    // quantized = vq[best_k]
    {
        const float4* vr4 = reinterpret_cast<const float4*>(vq + (size_t)best_k * DIM);
        float4* q4 = reinterpret_cast<float4*>(q_out + (size_t)tok * DIM);
        #pragma unroll
        for (int i = 0; i < DIM / 4; i++) q4[i] = vr4[i];
    }
    // segment sums
    {
        float* cs = g_cs + (size_t)best_k * DIM;
        #pragma unroll
        for (int d = 0; d < DIM; d++) atomicAdd(cs + d, xr[d]);
        atomicAdd(&g_cn[best_k], 1.0f);
    }
}

// ---------------- finalize: EMA + outputs, re-zero scratch ----------------
__global__ void finalize_kernel(
    const float* __restrict__ centroid_sum,
    const float* __restrict__ centroid_n,
    float* __restrict__ out_vq,
    float* __restrict__ out_cs,
    float* __restrict__ out_cn)
{
    int k = blockIdx.x;
    int d = threadIdx.x;
    float cs_acc = g_cs[k * DIM + d];
    float cn_acc = g_cn[k];
    __syncthreads();
    g_cs[k * DIM + d] = 0.0f;
    if (d == 0) g_cn[k] = 0.0f;

    float cs_new = centroid_sum[k * DIM + d] * GAMMA + cs_acc * (1.0f - GAMMA);
    float cn_new = centroid_n[k] * GAMMA + cn_acc * (1.0f - GAMMA);
    out_vq[k * DIM + d] = cs_new / cn_new;
    out_cs[k * DIM + d] = cs_new;
    if (d == 0) out_cn[k] = cn_new;
}

extern "C" void kernel_launch(void* const* d_in, const int* in_sizes, int n_in,
                              void* d_out, int out_size) {
    const float* x  = (const float*)d_in[0];   // [N, 64]
    const float* vq = (const float*)d_in[1];   // [512, 64]
    const float* cs = (const float*)d_in[2];   // [512, 64]
    const float* cn = (const float*)d_in[3];   // [512]

    float* out    = (float*)d_out;
    float* q_out  = out;                        // [N, 64]
    float* vq_out = out + (size_t)N_TOK * DIM;  // [512, 64]
    float* cs_out = vq_out + (size_t)KCB * DIM; // [512, 64]
    float* cn_out = cs_out + (size_t)KCB * DIM; // [512]

    cudaFuncSetAttribute(assign_kernel, cudaFuncAttributeMaxDynamicSharedMemorySize, SMEM_BYTES);

    init_kernel<<<KCB, DIM>>>(vq);
    assign_kernel<<<N_TOK / TOK_CTA, TPB, SMEM_BYTES>>>(x, vq, q_out);
    finalize_kernel<<<KCB, DIM>>>(cs, cn, vq_out, cs_out, cn_out);
}